// round 16
// baseline (speedup 1.0000x reference)
#include <cuda_runtime.h>
#include <cuda_bf16.h>
#include <cstdint>

#define NN 50000
#define EE 600000
#define HH 128
#define GG 500
#define CC 10
#define BN_EPS_F 1e-5f

#define WPAD 136
#define ASTRIDE (WPAD * 2)
#define NCHUNK ((NN + 1023) / 1024)   // 49
#define EB 8

// ---------------- scratch (device globals) ----------------------------------
__device__ int   g_is64;
__device__ float g_h1[NN * HH];
__device__ float g_p [2 * GG * HH];
__device__ int   g_rowptr[NN + 1];
__device__ int   g_cursor[NN];
__device__ int   g_adj[EE];
__device__ int   g_bsum[NCHUNK];
__device__ __align__(16) unsigned short g_wh[4][HH * WPAD];
__device__ __align__(16) unsigned short g_wl[4][HH * WPAD];
__device__ float g_scv[2][HH], g_shv[2][HH], g_bavv[2][HH], g_bb2v[2][HH];

// ---------------- helpers ----------------------------------------------------
__device__ __forceinline__ uint32_t smem_u32(const void* p) {
    uint32_t a;
    asm("{ .reg .u64 t; cvta.to.shared.u64 t, %1; cvt.u32.u64 %0, t; }" : "=r"(a) : "l"(p));
    return a;
}
__device__ __forceinline__ void mma_bf16(float* d, const uint32_t* a, uint32_t b0, uint32_t b1) {
    asm volatile("mma.sync.aligned.m16n8k16.row.col.f32.bf16.bf16.f32 "
                 "{%0,%1,%2,%3}, {%4,%5,%6,%7}, {%8,%9}, {%0,%1,%2,%3};"
                 : "+f"(d[0]), "+f"(d[1]), "+f"(d[2]), "+f"(d[3])
                 : "r"(a[0]), "r"(a[1]), "r"(a[2]), "r"(a[3]), "r"(b0), "r"(b1));
}
__device__ __forceinline__ void ldsm4(uint32_t* r, uint32_t addr) {
    asm volatile("ldmatrix.sync.aligned.m8n8.x4.shared.b16 {%0,%1,%2,%3}, [%4];"
                 : "=r"(r[0]), "=r"(r[1]), "=r"(r[2]), "=r"(r[3]) : "r"(addr));
}
__device__ __forceinline__ void ldsm4t(uint32_t* r, uint32_t addr) {
    asm volatile("ldmatrix.sync.aligned.m8n8.x4.trans.shared.b16 {%0,%1,%2,%3}, [%4];"
                 : "=r"(r[0]), "=r"(r[1]), "=r"(r[2]), "=r"(r[3]) : "r"(addr));
}
__device__ __forceinline__ void cp_async16(uint32_t dst, const void* src) {
    asm volatile("cp.async.cg.shared.global [%0], [%1], 16;" :: "r"(dst), "l"(src));
}
#define CP_COMMIT() asm volatile("cp.async.commit_group;" ::: "memory")
#define CP_WAIT0()  asm volatile("cp.async.wait_group 0;" ::: "memory")

__device__ __forceinline__ void split_bf(float v, unsigned short& h, unsigned short& l) {
    __nv_bfloat16 bh = __float2bfloat16(v);
    float r = v - __bfloat162float(bh);
    __nv_bfloat16 bl = __float2bfloat16(r);
    h = reinterpret_cast<unsigned short&>(bh);
    l = reinterpret_cast<unsigned short&>(bl);
}
__device__ __forceinline__ void split_pack2(float a, float b, uint32_t& hp, uint32_t& lp) {
    unsigned short h0, l0, h1, l1;
    split_bf(a, h0, l0); split_bf(b, h1, l1);
    hp = (uint32_t)h0 | ((uint32_t)h1 << 16);
    lp = (uint32_t)l0 | ((uint32_t)l1 << 16);
}
__device__ __forceinline__ void red_add_f32(float* p, float v) {
    asm volatile("red.global.add.f32 [%0], %1;" :: "l"(p), "f"(v) : "memory");
}
__device__ __forceinline__ int load_index(const void* p, long long i, int is64) {
    return is64 ? (int)((const long long*)p)[i] : ((const int*)p)[i];
}

// ---------------- zero + detect + weight split + BN fold --------------------
__global__ void zero_kernel(const int* __restrict__ e,
                            const float* __restrict__ W1a, const float* __restrict__ W1b,
                            const float* __restrict__ W2a, const float* __restrict__ W2b,
                            const float* __restrict__ b1a, const float* __restrict__ b1b,
                            const float* __restrict__ g1,  const float* __restrict__ be1,
                            const float* __restrict__ m1,  const float* __restrict__ v1,
                            const float* __restrict__ b2a, const float* __restrict__ b2b,
                            const float* __restrict__ g2,  const float* __restrict__ be2,
                            const float* __restrict__ m2,  const float* __restrict__ v2) {
    int i = blockIdx.x * blockDim.x + threadIdx.x;
    if (i == 0) {
        int acc = 0;
#pragma unroll
        for (int k = 0; k < 64; k++) acc |= e[2 * k + 1];
        g_is64 = (acc == 0);
    }
    if (i < NN) g_cursor[i] = 0;
    if (i < 2 * GG * HH / 4)
        ((float4*)g_p)[i] = make_float4(0.f, 0.f, 0.f, 0.f);

    // weight split: 2 consecutive n-elements per thread, u32 stores
    if (i < 2 * HH * HH) {
        int w = i >> 13;                 // 8192 pairs per weight
        int pix = i & 8191;
        int k = pix >> 6, n2 = (pix & 63) * 2;
        const float* Wp = (w == 0) ? W1a : (w == 1) ? W1b : (w == 2) ? W2a : W2b;
        const float* row = Wp + k * HH + n2;
        uint32_t hp, lp;
        split_pack2(row[0], row[1], hp, lp);
        *(uint32_t*)&g_wh[w][k * WPAD + n2] = hp;
        *(uint32_t*)&g_wl[w][k * WPAD + n2] = lp;
    }
    if (i < HH) {
        float s = g1[i] * rsqrtf(v1[i] + BN_EPS_F);
        g_scv[0][i] = s;
        g_shv[0][i] = (b1a[i] - m1[i]) * s + be1[i];
        g_bavv[0][i] = b1a[i];
        g_bb2v[0][i] = b1b[i];
    } else if (i < 2 * HH) {
        int c = i - HH;
        float s = g2[c] * rsqrtf(v2[c] + BN_EPS_F);
        g_scv[1][c] = s;
        g_shv[1][c] = be2[c] - m2[c] * s;
        g_bavv[1][c] = b2a[c];
        g_bb2v[1][c] = b2b[c];
    }
}

// ---------------- CSR build --------------------------------------------------
__global__ void deg_kernel(const void* __restrict__ eidx) {
    int t = blockIdx.x * blockDim.x + threadIdx.x;
    int stride = gridDim.x * blockDim.x;
    int is64 = g_is64;
#pragma unroll
    for (int q = 0; q < EB; q++) {
        int e = t + q * stride;
        if (e < EE) {
            int dst = load_index(eidx, (long long)EE + e, is64);
            atomicAdd(&g_cursor[dst], 1);
        }
    }
}

__global__ void sums_kernel() {
    __shared__ int sdata[32];
    int tid = threadIdx.x, lane = tid & 31, wid = tid >> 5;
    int i = blockIdx.x * 1024 + tid;
    int v = (i < NN) ? g_cursor[i] : 0;
#pragma unroll
    for (int off = 16; off; off >>= 1) v += __shfl_xor_sync(0xffffffffu, v, off);
    if (lane == 0) sdata[wid] = v;
    __syncthreads();
    if (wid == 0) {
        int t = sdata[lane];
#pragma unroll
        for (int off = 16; off; off >>= 1) t += __shfl_xor_sync(0xffffffffu, t, off);
        if (lane == 0) g_bsum[blockIdx.x] = t;
    }
}

__global__ void apply_kernel() {
    __shared__ int wsum[32];
    __shared__ int boff_s;
    int tid = threadIdx.x, lane = tid & 31, wid = tid >> 5;
    if (wid == 0) {
        int b = blockIdx.x;
        int v = 0;
        if (lane < NCHUNK && lane < b) v += g_bsum[lane];
        if (32 + lane < NCHUNK && 32 + lane < b) v += g_bsum[32 + lane];
#pragma unroll
        for (int off = 16; off; off >>= 1) v += __shfl_xor_sync(0xffffffffu, v, off);
        if (lane == 0) boff_s = v;
    }
    int i = blockIdx.x * 1024 + tid;
    int v = (i < NN) ? g_cursor[i] : 0;
    int incl = v;
#pragma unroll
    for (int off = 1; off < 32; off <<= 1) {
        int t = __shfl_up_sync(0xffffffffu, incl, off);
        if (lane >= off) incl += t;
    }
    if (lane == 31) wsum[wid] = incl;
    __syncthreads();
    if (wid == 0) {
        int t = wsum[lane];
        int ti = t;
#pragma unroll
        for (int off = 1; off < 32; off <<= 1) {
            int u = __shfl_up_sync(0xffffffffu, ti, off);
            if (lane >= off) ti += u;
        }
        wsum[lane] = ti - t;
    }
    __syncthreads();
    int excl = boff_s + wsum[wid] + (incl - v);
    if (i < NN) { g_rowptr[i] = excl; g_cursor[i] = excl; }
    if (i == NN - 1) g_rowptr[NN] = excl + v;
}

__global__ void fill_kernel(const void* __restrict__ eidx) {
    int t = blockIdx.x * blockDim.x + threadIdx.x;
    int stride = gridDim.x * blockDim.x;
    int is64 = g_is64;
#pragma unroll
    for (int q = 0; q < EB; q++) {
        int e = t + q * stride;
        if (e < EE) {
            int src = load_index(eidx, e, is64);
            int dst = load_index(eidx, (long long)EE + e, is64);
            int pos = atomicAdd(&g_cursor[dst], 1);
            g_adj[pos] = src;
        }
    }
}

// ---------------- bf16 split GEMM core: 64x128 @ 128x128 -------------------
__device__ __forceinline__ void gemm_core(uint32_t sbA, uint32_t sbW,
                                          int mrow0, int ncol0, int lane,
                                          float acc[2][4][4]) {
    const uint32_t aAddr0 = sbA + (mrow0 + (lane & 15)) * ASTRIDE + ((lane >> 4) * 8) * 2;
    const uint32_t bAddr0 = sbW + (lane & 15) * ASTRIDE + (ncol0 + (lane >> 4) * 8) * 2;
#pragma unroll
    for (int k0 = 0; k0 < 128; k0 += 16) {
        uint32_t ah[2][4], al[2][4], bh[2][4], bl[2][4];
        uint32_t aA = aAddr0 + k0 * 2;
        ldsm4(ah[0], aA);
        ldsm4(ah[1], aA + 16 * ASTRIDE);
        ldsm4(al[0], aA + 17408);
        ldsm4(al[1], aA + 17408 + 16 * ASTRIDE);
        uint32_t bA = bAddr0 + k0 * ASTRIDE;
        ldsm4t(bh[0], bA);
        ldsm4t(bh[1], bA + 32);
        ldsm4t(bl[0], bA + 34816);
        ldsm4t(bl[1], bA + 34816 + 32);
#pragma unroll
        for (int mi = 0; mi < 2; mi++)
#pragma unroll
            for (int ni = 0; ni < 4; ni++) {
                uint32_t b0 = bh[ni >> 1][(ni & 1) * 2], b1 = bh[ni >> 1][(ni & 1) * 2 + 1];
                mma_bf16(acc[mi][ni], ah[mi], b0, b1);
                mma_bf16(acc[mi][ni], al[mi], b0, b1);
                uint32_t c0 = bl[ni >> 1][(ni & 1) * 2], c1 = bl[ni >> 1][(ni & 1) * 2 + 1];
                mma_bf16(acc[mi][ni], ah[mi], c0, c1);
            }
    }
}

// ---------------- fused MLP (staged gather + 2 GEMMs + epilogues + pool) ----
#define SM_A    0
#define SM_W    34816
#define SM_RP   104448
#define SM_IDX  104720
#define IDX_CAP 2048
#define MLP_SMEM (SM_IDX + IDX_CAP * 4)   // 112912 B -> 2 CTAs/SM
#define MROWS 64
#define HB_STRIDE 132

template <int CONV>
__global__ void __launch_bounds__(256, 2)
mlp_kernel(const float* __restrict__ x, const void* __restrict__ batch) {
    extern __shared__ char smem[];
    const uint32_t sb = smem_u32(smem);
    const int tid = threadIdx.x;
    const int lane = tid & 31, wid = tid >> 5;
    const int mrow0 = (wid & 1) * 32;
    const int ncol0 = (wid >> 1) * 32;
    const int row0 = blockIdx.x * MROWS;
    const int L = CONV - 1;

    const float* base = (CONV == 1) ? x : (const float*)g_h1;
    float* pool = (CONV == 1) ? g_p : (g_p + GG * HH);
    int* rp   = (int*)(smem + SM_RP);
    int* sidx = (int*)(smem + SM_IDX);

    // ---- kick off async Wa hi/lo load ----
    {
        const uint4* wh = (const uint4*)g_wh[2 * L];
        const uint4* wl = (const uint4*)g_wl[2 * L];
        for (int i = tid; i < 2176; i += 256) {
            cp_async16(sb + SM_W + i * 16,         wh + i);
            cp_async16(sb + SM_W + 34816 + i * 16, wl + i);
        }
        CP_COMMIT();
    }

    // ---- stage rowptr slice + contiguous adjacency range ----
    const int rtop = (row0 + MROWS < NN) ? (row0 + MROWS) : NN;
    if (tid < 65) {
        int gi = row0 + tid;
        rp[tid] = g_rowptr[(gi < rtop) ? gi : rtop];
    }
    __syncthreads();
    const int s0 = rp[0];
    const int cnt = rp[64] - s0;
    const int stg = (cnt < IDX_CAP) ? cnt : IDX_CAP;
    for (int i = tid; i < stg; i += 256) sidx[i] = g_adj[s0 + i];
    __syncthreads();

    // ---- gather A-tile: a[r] = base[r] + sum_{j in adj(r)} base[j] ----
    for (int rr = wid; rr < MROWS; rr += 8) {
        int grow = row0 + rr;
        float4 acc = make_float4(0.f, 0.f, 0.f, 0.f);
        if (grow < NN) {
            acc = ((const float4*)(base + (size_t)grow * HH))[lane];
            int s = rp[rr], e = rp[rr + 1];
            int j = s;
            for (; j + 4 <= e; j += 4) {
                int o = j - s0;
                int n0, n1, n2, n3;
                if (o + 3 < IDX_CAP) {
                    n0 = sidx[o]; n1 = sidx[o + 1]; n2 = sidx[o + 2]; n3 = sidx[o + 3];
                } else {
                    n0 = g_adj[j]; n1 = g_adj[j + 1]; n2 = g_adj[j + 2]; n3 = g_adj[j + 3];
                }
                float4 v0 = ((const float4*)(base + (size_t)n0 * HH))[lane];
                float4 v1 = ((const float4*)(base + (size_t)n1 * HH))[lane];
                float4 v2 = ((const float4*)(base + (size_t)n2 * HH))[lane];
                float4 v3 = ((const float4*)(base + (size_t)n3 * HH))[lane];
                acc.x += v0.x + v1.x + v2.x + v3.x;
                acc.y += v0.y + v1.y + v2.y + v3.y;
                acc.z += v0.z + v1.z + v2.z + v3.z;
                acc.w += v0.w + v1.w + v2.w + v3.w;
            }
            for (; j < e; j++) {
                int o = j - s0;
                int n = (o < IDX_CAP) ? sidx[o] : g_adj[j];
                float4 v = ((const float4*)(base + (size_t)n * HH))[lane];
                acc.x += v.x; acc.y += v.y; acc.z += v.z; acc.w += v.w;
            }
        }
        uint32_t h0, l0, h1, l1;
        split_pack2(acc.x, acc.y, h0, l0);
        split_pack2(acc.z, acc.w, h1, l1);
        int off = rr * ASTRIDE + lane * 8;
        *(uint2*)(smem + SM_A + off)         = make_uint2(h0, h1);
        *(uint2*)(smem + SM_A + 17408 + off) = make_uint2(l0, l1);
    }
    CP_WAIT0();
    __syncthreads();

    float acc[2][4][4];
#pragma unroll
    for (int a = 0; a < 2; a++)
#pragma unroll
        for (int b = 0; b < 4; b++)
#pragma unroll
            for (int c = 0; c < 4; c++) acc[a][b][c] = 0.f;

    gemm_core(sb + SM_A, sb + SM_W, mrow0, ncol0, lane, acc);
    __syncthreads();

    // ---- async Wb load overlaps epilogue 1 ----
    {
        const uint4* wh = (const uint4*)g_wh[2 * L + 1];
        const uint4* wl = (const uint4*)g_wl[2 * L + 1];
        for (int i = tid; i < 2176; i += 256) {
            cp_async16(sb + SM_W + i * 16,         wh + i);
            cp_async16(sb + SM_W + 34816 + i * 16, wl + i);
        }
        CP_COMMIT();
    }

    // ---- epilogue 1: t back into A smem as bf16 hi/lo ----
    {
        const int rl = mrow0 + (lane >> 2);
        const int cl = (lane & 3) * 2;
#pragma unroll
        for (int mi = 0; mi < 2; mi++) {
            int r = rl + mi * 16;
#pragma unroll
            for (int ni = 0; ni < 4; ni++) {
                int c = ncol0 + ni * 8 + cl;
                float sc0 = g_scv[L][c], sc1 = g_scv[L][c + 1];
                float sh0 = g_shv[L][c], sh1 = g_shv[L][c + 1];
                float d0 = acc[mi][ni][0], d1 = acc[mi][ni][1];
                float d2 = acc[mi][ni][2], d3 = acc[mi][ni][3];
                float t0, t1, t2, t3;
                if (CONV == 1) {
                    t0 = fmaxf(d0 * sc0 + sh0, 0.f);
                    t1 = fmaxf(d1 * sc1 + sh1, 0.f);
                    t2 = fmaxf(d2 * sc0 + sh0, 0.f);
                    t3 = fmaxf(d3 * sc1 + sh1, 0.f);
                } else {
                    float bv0 = g_bavv[L][c], bv1 = g_bavv[L][c + 1];
                    t0 = fmaxf(d0 + bv0, 0.f) * sc0 + sh0;
                    t1 = fmaxf(d1 + bv1, 0.f) * sc1 + sh1;
                    t2 = fmaxf(d2 + bv0, 0.f) * sc0 + sh0;
                    t3 = fmaxf(d3 + bv1, 0.f) * sc1 + sh1;
                }
                uint32_t hp, lp;
                split_pack2(t0, t1, hp, lp);
                int off = r * ASTRIDE + c * 2;
                *(uint32_t*)(smem + SM_A + off)         = hp;
                *(uint32_t*)(smem + SM_A + 17408 + off) = lp;
                split_pack2(t2, t3, hp, lp);
                off += 8 * ASTRIDE;
                *(uint32_t*)(smem + SM_A + off)         = hp;
                *(uint32_t*)(smem + SM_A + 17408 + off) = lp;
            }
        }
    }
    CP_WAIT0();
    __syncthreads();

#pragma unroll
    for (int a = 0; a < 2; a++)
#pragma unroll
        for (int b = 0; b < 4; b++)
#pragma unroll
            for (int c = 0; c < 4; c++) acc[a][b][c] = 0.f;

    gemm_core(sb + SM_A, sb + SM_W, mrow0, ncol0, lane, acc);
    __syncthreads();   // all warps done with smem reads; W/A regions reusable

    // ---- epilogue 2: h = relu(d + bb2); h1 store (conv1); stage h in smem --
    float* hbuf = (float*)(smem + SM_W);   // [64][HB_STRIDE]
    int* bids = rp;                        // reuse rowptr cache region
    {
        const int is64 = g_is64;
        if (tid < MROWS) {
            int grow = row0 + tid;
            bids[tid] = (grow < NN) ? load_index(batch, grow, is64) : -1;
        }
        const int rl = mrow0 + (lane >> 2);
        const int cl = (lane & 3) * 2;
#pragma unroll
        for (int mi = 0; mi < 2; mi++) {
            int ra = rl + mi * 16;      // local rows ra, ra+8
            int ga = row0 + ra;
            int gb = ga + 8;
#pragma unroll
            for (int ni = 0; ni < 4; ni++) {
                int c = ncol0 + ni * 8 + cl;
                float bv0 = g_bb2v[L][c], bv1 = g_bb2v[L][c + 1];
                float h0 = fmaxf(acc[mi][ni][0] + bv0, 0.f);
                float h1 = fmaxf(acc[mi][ni][1] + bv1, 0.f);
                float h2 = fmaxf(acc[mi][ni][2] + bv0, 0.f);
                float h3 = fmaxf(acc[mi][ni][3] + bv1, 0.f);
                *(float2*)(hbuf + ra * HB_STRIDE + c)       = make_float2(h0, h1);
                *(float2*)(hbuf + (ra + 8) * HB_STRIDE + c) = make_float2(h2, h3);
                if (CONV == 1) {
                    if (ga < NN)
                        *(float2*)(g_h1 + (size_t)ga * HH + c) = make_float2(h0, h1);
                    if (gb < NN)
                        *(float2*)(g_h1 + (size_t)gb * HH + c) = make_float2(h2, h3);
                }
            }
        }
    }
    __syncthreads();

    // ---- segmented pool reduction: one atomic per (graph-segment, column) --
    {
        const int col = tid & 127;
        const int r0 = (tid >> 7) * 32;
        float sum = 0.f;
        int cur = bids[r0];
#pragma unroll 4
        for (int r = r0; r < r0 + 32; r++) {
            int b = bids[r];
            if (b != cur) {
                if (cur >= 0) red_add_f32(pool + (size_t)cur * HH + col, sum);
                sum = 0.f;
                cur = b;
            }
            sum += hbuf[r * HB_STRIDE + col];
        }
        if (cur >= 0) red_add_f32(pool + (size_t)cur * HH + col, sum);
    }
}

// ---------------- head: relu([p1,p2]@Wl1 + bl1) @ Wl2 + bl2 ----------------
#define HZ_STRIDE 264
#define HEAD_SMEM ((256 * 64 + 4 * HZ_STRIDE + 64 * CC + 64 + 16) * 4)

__global__ void __launch_bounds__(128)
head_kernel(const float* __restrict__ Wl1, const float* __restrict__ bl1,
            const float* __restrict__ Wl2, const float* __restrict__ bl2,
            float* __restrict__ out) {
    extern __shared__ float smemf[];
    float* Wl1s = smemf;                        // [256][64]
    float* zs   = smemf + 256 * 64;             // [4][HZ_STRIDE]
    float* Wl2s = zs + 4 * HZ_STRIDE;           // [64][10]
    float* bl1s = Wl2s + 64 * CC;               // [64]
    float* bl2s = bl1s + 64;                    // [10]

    int tid = threadIdx.x;
    for (int i = tid; i < 4 * 256; i += 128) {
        int w = i >> 8, k = i & 255;
        int r = blockIdx.x * 4 + w;
        float v = 0.f;
        if (r < GG)
            v = (k < 128) ? g_p[(size_t)r * HH + k]
                          : g_p[GG * HH + (size_t)r * HH + (k - 128)];
        zs[w * HZ_STRIDE + k] = v;
    }
    for (int i = tid; i < 256 * 64 / 4; i += 128)
        ((float4*)Wl1s)[i] = ((const float4*)Wl1)[i];
    for (int i = tid; i < 64 * CC; i += 128) Wl2s[i] = Wl2[i];
    if (tid < 64) bl1s[tid] = bl1[tid];
    else if (tid < 64 + CC) bl2s[tid - 64] = bl2[tid - 64];
    __syncthreads();

    int lane = tid & 31;
    int warp = tid >> 5;
    int r = blockIdx.x * 4 + warp;
    if (r >= GG) return;

    float h0 = bl1s[2 * lane], h1v = bl1s[2 * lane + 1];
    const float* z = zs + warp * HZ_STRIDE;
#pragma unroll 8
    for (int k = 0; k < 256; ++k) {
        float v = z[k];
        float2 w = ((const float2*)Wl1s)[k * 32 + lane];
        h0 += v * w.x; h1v += v * w.y;
    }
    h0 = fmaxf(h0, 0.f); h1v = fmaxf(h1v, 0.f);

#pragma unroll
    for (int c = 0; c < CC; c++) {
        float part = h0 * Wl2s[(2 * lane) * CC + c] + h1v * Wl2s[(2 * lane + 1) * CC + c];
#pragma unroll
        for (int off = 16; off; off >>= 1)
            part += __shfl_xor_sync(0xffffffffu, part, off);
        if (lane == 0) out[r * CC + c] = part + bl2s[c];
    }
}

// ---------------- launch ----------------------------------------------------
extern "C" void kernel_launch(void* const* d_in, const int* in_sizes, int n_in,
                              void* d_out, int out_size) {
    const float* x    = (const float*)d_in[0];
    const void*  eidx = d_in[1];
    const void*  batch= d_in[2];
    const float* W1a  = (const float*)d_in[3];
    const float* b1a  = (const float*)d_in[4];
    const float* g1   = (const float*)d_in[5];
    const float* be1  = (const float*)d_in[6];
    const float* m1   = (const float*)d_in[7];
    const float* v1   = (const float*)d_in[8];
    const float* W1b  = (const float*)d_in[9];
    const float* b1b  = (const float*)d_in[10];
    const float* W2a  = (const float*)d_in[11];
    const float* b2a  = (const float*)d_in[12];
    const float* g2   = (const float*)d_in[13];
    const float* be2  = (const float*)d_in[14];
    const float* m2   = (const float*)d_in[15];
    const float* v2   = (const float*)d_in[16];
    const float* W2b  = (const float*)d_in[17];
    const float* b2b  = (const float*)d_in[18];
    const float* Wl1  = (const float*)d_in[19];
    const float* bl1  = (const float*)d_in[20];
    const float* Wl2  = (const float*)d_in[21];
    const float* bl2  = (const float*)d_in[22];
    float* out = (float*)d_out;

    cudaFuncSetAttribute(mlp_kernel<1>, cudaFuncAttributeMaxDynamicSharedMemorySize, MLP_SMEM);
    cudaFuncSetAttribute(mlp_kernel<2>, cudaFuncAttributeMaxDynamicSharedMemorySize, MLP_SMEM);
    cudaFuncSetAttribute(head_kernel,   cudaFuncAttributeMaxDynamicSharedMemorySize, HEAD_SMEM);

    zero_kernel<<<256, 256>>>(
        (const int*)eidx, W1a, W1b, W2a, W2b,
        b1a, b1b, g1, be1, m1, v1, b2a, b2b, g2, be2, m2, v2);

    int egrid = (EE + 256 * EB - 1) / (256 * EB);
    deg_kernel<<<egrid, 256>>>(eidx);
    sums_kernel<<<NCHUNK, 1024>>>();
    apply_kernel<<<NCHUNK, 1024>>>();
    fill_kernel<<<egrid, 256>>>(eidx);

    mlp_kernel<1><<<(NN + MROWS - 1) / MROWS, 256, MLP_SMEM>>>(x, batch);
    mlp_kernel<2><<<(NN + MROWS - 1) / MROWS, 256, MLP_SMEM>>>(x /*unused*/, batch);

    head_kernel<<<125, 128, HEAD_SMEM>>>(Wl1, bl1, Wl2, bl2, out);
}

// round 17
// speedup vs baseline: 1.5445x; 1.5445x over previous
#include <cuda_runtime.h>
#include <cuda_bf16.h>
#include <cstdint>

#define NN 50000
#define EE 600000
#define HH 128
#define GG 500
#define CC 10
#define BN_EPS_F 1e-5f

#define WPAD 136
#define ASTRIDE (WPAD * 2)
#define NCHUNK ((NN + 1023) / 1024)   // 49
#define EB 4

// ---------------- scratch (device globals) ----------------------------------
__device__ int   g_is64;
__device__ float g_h1[NN * HH];
__device__ float g_p [2 * GG * HH];
__device__ int   g_rowptr[NN + 1];
__device__ int   g_cursor[NN];
__device__ int   g_adj[EE];
__device__ int   g_bsum[NCHUNK];
__device__ __align__(16) unsigned short g_wh[4][HH * WPAD];
__device__ __align__(16) unsigned short g_wl[4][HH * WPAD];
__device__ float g_scv[2][HH], g_shv[2][HH], g_bavv[2][HH], g_bb2v[2][HH];

// ---------------- helpers ----------------------------------------------------
__device__ __forceinline__ uint32_t smem_u32(const void* p) {
    uint32_t a;
    asm("{ .reg .u64 t; cvta.to.shared.u64 t, %1; cvt.u32.u64 %0, t; }" : "=r"(a) : "l"(p));
    return a;
}
__device__ __forceinline__ void mma_bf16(float* d, const uint32_t* a, uint32_t b0, uint32_t b1) {
    asm volatile("mma.sync.aligned.m16n8k16.row.col.f32.bf16.bf16.f32 "
                 "{%0,%1,%2,%3}, {%4,%5,%6,%7}, {%8,%9}, {%0,%1,%2,%3};"
                 : "+f"(d[0]), "+f"(d[1]), "+f"(d[2]), "+f"(d[3])
                 : "r"(a[0]), "r"(a[1]), "r"(a[2]), "r"(a[3]), "r"(b0), "r"(b1));
}
__device__ __forceinline__ void ldsm4(uint32_t* r, uint32_t addr) {
    asm volatile("ldmatrix.sync.aligned.m8n8.x4.shared.b16 {%0,%1,%2,%3}, [%4];"
                 : "=r"(r[0]), "=r"(r[1]), "=r"(r[2]), "=r"(r[3]) : "r"(addr));
}
__device__ __forceinline__ void ldsm4t(uint32_t* r, uint32_t addr) {
    asm volatile("ldmatrix.sync.aligned.m8n8.x4.trans.shared.b16 {%0,%1,%2,%3}, [%4];"
                 : "=r"(r[0]), "=r"(r[1]), "=r"(r[2]), "=r"(r[3]) : "r"(addr));
}
__device__ __forceinline__ void cp_async16(uint32_t dst, const void* src) {
    asm volatile("cp.async.cg.shared.global [%0], [%1], 16;" :: "r"(dst), "l"(src));
}
#define CP_COMMIT() asm volatile("cp.async.commit_group;" ::: "memory")
#define CP_WAIT0()  asm volatile("cp.async.wait_group 0;" ::: "memory")

__device__ __forceinline__ void split_bf(float v, unsigned short& h, unsigned short& l) {
    __nv_bfloat16 bh = __float2bfloat16(v);
    float r = v - __bfloat162float(bh);
    __nv_bfloat16 bl = __float2bfloat16(r);
    h = reinterpret_cast<unsigned short&>(bh);
    l = reinterpret_cast<unsigned short&>(bl);
}
__device__ __forceinline__ void split_pack2(float a, float b, uint32_t& hp, uint32_t& lp) {
    unsigned short h0, l0, h1, l1;
    split_bf(a, h0, l0); split_bf(b, h1, l1);
    hp = (uint32_t)h0 | ((uint32_t)h1 << 16);
    lp = (uint32_t)l0 | ((uint32_t)l1 << 16);
}
__device__ __forceinline__ void red_add_f32(float* p, float v) {
    asm volatile("red.global.add.f32 [%0], %1;" :: "l"(p), "f"(v) : "memory");
}
__device__ __forceinline__ int load_index(const void* p, long long i, int is64) {
    return is64 ? (int)((const long long*)p)[i] : ((const int*)p)[i];
}

// ---------------- zero + detect + weight split + BN fold --------------------
__global__ void zero_kernel(const int* __restrict__ e,
                            const float* __restrict__ W1a, const float* __restrict__ W1b,
                            const float* __restrict__ W2a, const float* __restrict__ W2b,
                            const float* __restrict__ b1a, const float* __restrict__ b1b,
                            const float* __restrict__ g1,  const float* __restrict__ be1,
                            const float* __restrict__ m1,  const float* __restrict__ v1,
                            const float* __restrict__ b2a, const float* __restrict__ b2b,
                            const float* __restrict__ g2,  const float* __restrict__ be2,
                            const float* __restrict__ m2,  const float* __restrict__ v2) {
    int i = blockIdx.x * blockDim.x + threadIdx.x;
    if (i == 0) {
        int acc = 0;
#pragma unroll
        for (int k = 0; k < 64; k++) acc |= e[2 * k + 1];
        g_is64 = (acc == 0);
    }
    if (i < NN) g_cursor[i] = 0;
    if (i < 2 * GG * HH / 4)
        ((float4*)g_p)[i] = make_float4(0.f, 0.f, 0.f, 0.f);

    if (i < 4 * HH * HH) {
        int w = i >> 14;
        int eidx = i & 16383;
        int k = eidx >> 7, n = eidx & 127;
        const float* Wp = (w == 0) ? W1a : (w == 1) ? W1b : (w == 2) ? W2a : W2b;
        unsigned short h, l;
        split_bf(Wp[eidx], h, l);
        g_wh[w][k * WPAD + n] = h;
        g_wl[w][k * WPAD + n] = l;
    }
    if (i < HH) {
        float s = g1[i] * rsqrtf(v1[i] + BN_EPS_F);
        g_scv[0][i] = s;
        g_shv[0][i] = (b1a[i] - m1[i]) * s + be1[i];
        g_bavv[0][i] = b1a[i];
        g_bb2v[0][i] = b1b[i];
    } else if (i < 2 * HH) {
        int c = i - HH;
        float s = g2[c] * rsqrtf(v2[c] + BN_EPS_F);
        g_scv[1][c] = s;
        g_shv[1][c] = be2[c] - m2[c] * s;
        g_bavv[1][c] = b2a[c];
        g_bb2v[1][c] = b2b[c];
    }
}

// ---------------- CSR build --------------------------------------------------
__global__ void deg_kernel(const void* __restrict__ eidx) {
    int t = blockIdx.x * blockDim.x + threadIdx.x;
    int stride = gridDim.x * blockDim.x;
    int is64 = g_is64;
#pragma unroll
    for (int q = 0; q < EB; q++) {
        int e = t + q * stride;
        if (e < EE) {
            int dst = load_index(eidx, (long long)EE + e, is64);
            atomicAdd(&g_cursor[dst], 1);
        }
    }
}

__global__ void sums_kernel() {
    __shared__ int sdata[32];
    int tid = threadIdx.x, lane = tid & 31, wid = tid >> 5;
    int i = blockIdx.x * 1024 + tid;
    int v = (i < NN) ? g_cursor[i] : 0;
#pragma unroll
    for (int off = 16; off; off >>= 1) v += __shfl_xor_sync(0xffffffffu, v, off);
    if (lane == 0) sdata[wid] = v;
    __syncthreads();
    if (wid == 0) {
        int t = sdata[lane];
#pragma unroll
        for (int off = 16; off; off >>= 1) t += __shfl_xor_sync(0xffffffffu, t, off);
        if (lane == 0) g_bsum[blockIdx.x] = t;
    }
}

__global__ void apply_kernel() {
    __shared__ int wsum[32];
    __shared__ int boff_s;
    int tid = threadIdx.x, lane = tid & 31, wid = tid >> 5;
    if (wid == 0) {
        int b = blockIdx.x;
        int v = 0;
        if (lane < NCHUNK && lane < b) v += g_bsum[lane];
        if (32 + lane < NCHUNK && 32 + lane < b) v += g_bsum[32 + lane];
#pragma unroll
        for (int off = 16; off; off >>= 1) v += __shfl_xor_sync(0xffffffffu, v, off);
        if (lane == 0) boff_s = v;
    }
    int i = blockIdx.x * 1024 + tid;
    int v = (i < NN) ? g_cursor[i] : 0;
    int incl = v;
#pragma unroll
    for (int off = 1; off < 32; off <<= 1) {
        int t = __shfl_up_sync(0xffffffffu, incl, off);
        if (lane >= off) incl += t;
    }
    if (lane == 31) wsum[wid] = incl;
    __syncthreads();
    if (wid == 0) {
        int t = wsum[lane];
        int ti = t;
#pragma unroll
        for (int off = 1; off < 32; off <<= 1) {
            int u = __shfl_up_sync(0xffffffffu, ti, off);
            if (lane >= off) ti += u;
        }
        wsum[lane] = ti - t;
    }
    __syncthreads();
    int excl = boff_s + wsum[wid] + (incl - v);
    if (i < NN) { g_rowptr[i] = excl; g_cursor[i] = excl; }
    if (i == NN - 1) g_rowptr[NN] = excl + v;
}

__global__ void fill_kernel(const void* __restrict__ eidx) {
    int t = blockIdx.x * blockDim.x + threadIdx.x;
    int stride = gridDim.x * blockDim.x;
    int is64 = g_is64;
#pragma unroll
    for (int q = 0; q < EB; q++) {
        int e = t + q * stride;
        if (e < EE) {
            int src = load_index(eidx, e, is64);
            int dst = load_index(eidx, (long long)EE + e, is64);
            int pos = atomicAdd(&g_cursor[dst], 1);
            g_adj[pos] = src;
        }
    }
}

// ---------------- bf16 split GEMM core: 64x128 @ 128x128 -------------------
__device__ __forceinline__ void gemm_core(uint32_t sbA, uint32_t sbW,
                                          int mrow0, int ncol0, int lane,
                                          float acc[2][4][4]) {
    const uint32_t aAddr0 = sbA + (mrow0 + (lane & 15)) * ASTRIDE + ((lane >> 4) * 8) * 2;
    const uint32_t bAddr0 = sbW + (lane & 15) * ASTRIDE + (ncol0 + (lane >> 4) * 8) * 2;
#pragma unroll
    for (int k0 = 0; k0 < 128; k0 += 16) {
        uint32_t ah[2][4], al[2][4], bh[2][4], bl[2][4];
        uint32_t aA = aAddr0 + k0 * 2;
        ldsm4(ah[0], aA);
        ldsm4(ah[1], aA + 16 * ASTRIDE);
        ldsm4(al[0], aA + 17408);
        ldsm4(al[1], aA + 17408 + 16 * ASTRIDE);
        uint32_t bA = bAddr0 + k0 * ASTRIDE;
        ldsm4t(bh[0], bA);
        ldsm4t(bh[1], bA + 32);
        ldsm4t(bl[0], bA + 34816);
        ldsm4t(bl[1], bA + 34816 + 32);
#pragma unroll
        for (int mi = 0; mi < 2; mi++)
#pragma unroll
            for (int ni = 0; ni < 4; ni++) {
                uint32_t b0 = bh[ni >> 1][(ni & 1) * 2], b1 = bh[ni >> 1][(ni & 1) * 2 + 1];
                mma_bf16(acc[mi][ni], ah[mi], b0, b1);
                mma_bf16(acc[mi][ni], al[mi], b0, b1);
                uint32_t c0 = bl[ni >> 1][(ni & 1) * 2], c1 = bl[ni >> 1][(ni & 1) * 2 + 1];
                mma_bf16(acc[mi][ni], ah[mi], c0, c1);
            }
    }
}

// ---------------- fused MLP (staged gather + 2 GEMMs + epilogues + pool) ----
#define SM_A    0
#define SM_W    34816
#define SM_RP   104448
#define SM_IDX  104720
#define IDX_CAP 2048
#define MLP_SMEM (SM_IDX + IDX_CAP * 4)   // 112912 B -> 2 CTAs/SM
#define MROWS 64
#define HB_STRIDE 132

template <int CONV>
__global__ void __launch_bounds__(256, 2)
mlp_kernel(const float* __restrict__ x, const void* __restrict__ batch) {
    extern __shared__ char smem[];
    const uint32_t sb = smem_u32(smem);
    const int tid = threadIdx.x;
    const int lane = tid & 31, wid = tid >> 5;
    const int mrow0 = (wid & 1) * 32;
    const int ncol0 = (wid >> 1) * 32;
    const int row0 = blockIdx.x * MROWS;
    const int L = CONV - 1;

    const float* base = (CONV == 1) ? x : (const float*)g_h1;
    float* pool = (CONV == 1) ? g_p : (g_p + GG * HH);
    int* rp   = (int*)(smem + SM_RP);
    int* sidx = (int*)(smem + SM_IDX);

    // ---- kick off async Wa hi/lo load ----
    {
        const uint4* wh = (const uint4*)g_wh[2 * L];
        const uint4* wl = (const uint4*)g_wl[2 * L];
        for (int i = tid; i < 2176; i += 256) {
            cp_async16(sb + SM_W + i * 16,         wh + i);
            cp_async16(sb + SM_W + 34816 + i * 16, wl + i);
        }
        CP_COMMIT();
    }

    // ---- stage rowptr slice + contiguous adjacency range ----
    const int rtop = (row0 + MROWS < NN) ? (row0 + MROWS) : NN;
    if (tid < 65) {
        int gi = row0 + tid;
        rp[tid] = g_rowptr[(gi < rtop) ? gi : rtop];
    }
    __syncthreads();
    const int s0 = rp[0];
    const int cnt = rp[64] - s0;
    const int allin = (cnt <= IDX_CAP);
    const int stg = allin ? cnt : IDX_CAP;
    for (int i = tid; i < stg; i += 256) sidx[i] = g_adj[s0 + i];
    __syncthreads();

    // ---- gather A-tile: a[r] = base[r] + sum_{j in adj(r)} base[j] ----
    for (int rr = wid; rr < MROWS; rr += 8) {
        int grow = row0 + rr;
        float4 acc = make_float4(0.f, 0.f, 0.f, 0.f);
        if (grow < NN) {
            acc = ((const float4*)(base + (size_t)grow * HH))[lane];
            int s = rp[rr], e = rp[rr + 1];
            int j = s;
            if (allin) {
                // hot path: all indices staged in smem, no bounds checks
                for (; j + 4 <= e; j += 4) {
                    int o = j - s0;
                    int n0 = sidx[o], n1 = sidx[o + 1], n2 = sidx[o + 2], n3 = sidx[o + 3];
                    float4 v0 = ((const float4*)(base + (size_t)n0 * HH))[lane];
                    float4 v1 = ((const float4*)(base + (size_t)n1 * HH))[lane];
                    float4 v2 = ((const float4*)(base + (size_t)n2 * HH))[lane];
                    float4 v3 = ((const float4*)(base + (size_t)n3 * HH))[lane];
                    acc.x += v0.x + v1.x + v2.x + v3.x;
                    acc.y += v0.y + v1.y + v2.y + v3.y;
                    acc.z += v0.z + v1.z + v2.z + v3.z;
                    acc.w += v0.w + v1.w + v2.w + v3.w;
                }
                for (; j < e; j++) {
                    int n = sidx[j - s0];
                    float4 v = ((const float4*)(base + (size_t)n * HH))[lane];
                    acc.x += v.x; acc.y += v.y; acc.z += v.z; acc.w += v.w;
                }
            } else {
                for (; j + 4 <= e; j += 4) {
                    int o = j - s0;
                    int n0, n1, n2, n3;
                    if (o + 3 < IDX_CAP) {
                        n0 = sidx[o]; n1 = sidx[o + 1]; n2 = sidx[o + 2]; n3 = sidx[o + 3];
                    } else {
                        n0 = g_adj[j]; n1 = g_adj[j + 1]; n2 = g_adj[j + 2]; n3 = g_adj[j + 3];
                    }
                    float4 v0 = ((const float4*)(base + (size_t)n0 * HH))[lane];
                    float4 v1 = ((const float4*)(base + (size_t)n1 * HH))[lane];
                    float4 v2 = ((const float4*)(base + (size_t)n2 * HH))[lane];
                    float4 v3 = ((const float4*)(base + (size_t)n3 * HH))[lane];
                    acc.x += v0.x + v1.x + v2.x + v3.x;
                    acc.y += v0.y + v1.y + v2.y + v3.y;
                    acc.z += v0.z + v1.z + v2.z + v3.z;
                    acc.w += v0.w + v1.w + v2.w + v3.w;
                }
                for (; j < e; j++) {
                    int o = j - s0;
                    int n = (o < IDX_CAP) ? sidx[o] : g_adj[j];
                    float4 v = ((const float4*)(base + (size_t)n * HH))[lane];
                    acc.x += v.x; acc.y += v.y; acc.z += v.z; acc.w += v.w;
                }
            }
        }
        uint32_t h0, l0, h1, l1;
        split_pack2(acc.x, acc.y, h0, l0);
        split_pack2(acc.z, acc.w, h1, l1);
        int off = rr * ASTRIDE + lane * 8;
        *(uint2*)(smem + SM_A + off)         = make_uint2(h0, h1);
        *(uint2*)(smem + SM_A + 17408 + off) = make_uint2(l0, l1);
    }
    CP_WAIT0();
    __syncthreads();

    float acc[2][4][4];
#pragma unroll
    for (int a = 0; a < 2; a++)
#pragma unroll
        for (int b = 0; b < 4; b++)
#pragma unroll
            for (int c = 0; c < 4; c++) acc[a][b][c] = 0.f;

    gemm_core(sb + SM_A, sb + SM_W, mrow0, ncol0, lane, acc);
    __syncthreads();

    // ---- async Wb load overlaps epilogue 1 ----
    {
        const uint4* wh = (const uint4*)g_wh[2 * L + 1];
        const uint4* wl = (const uint4*)g_wl[2 * L + 1];
        for (int i = tid; i < 2176; i += 256) {
            cp_async16(sb + SM_W + i * 16,         wh + i);
            cp_async16(sb + SM_W + 34816 + i * 16, wl + i);
        }
        CP_COMMIT();
    }

    // ---- epilogue 1: t back into A smem as bf16 hi/lo ----
    {
        const int rl = mrow0 + (lane >> 2);
        const int cl = (lane & 3) * 2;
#pragma unroll
        for (int mi = 0; mi < 2; mi++) {
            int r = rl + mi * 16;
#pragma unroll
            for (int ni = 0; ni < 4; ni++) {
                int c = ncol0 + ni * 8 + cl;
                float sc0 = g_scv[L][c], sc1 = g_scv[L][c + 1];
                float sh0 = g_shv[L][c], sh1 = g_shv[L][c + 1];
                float d0 = acc[mi][ni][0], d1 = acc[mi][ni][1];
                float d2 = acc[mi][ni][2], d3 = acc[mi][ni][3];
                float t0, t1, t2, t3;
                if (CONV == 1) {
                    t0 = fmaxf(d0 * sc0 + sh0, 0.f);
                    t1 = fmaxf(d1 * sc1 + sh1, 0.f);
                    t2 = fmaxf(d2 * sc0 + sh0, 0.f);
                    t3 = fmaxf(d3 * sc1 + sh1, 0.f);
                } else {
                    float bv0 = g_bavv[L][c], bv1 = g_bavv[L][c + 1];
                    t0 = fmaxf(d0 + bv0, 0.f) * sc0 + sh0;
                    t1 = fmaxf(d1 + bv1, 0.f) * sc1 + sh1;
                    t2 = fmaxf(d2 + bv0, 0.f) * sc0 + sh0;
                    t3 = fmaxf(d3 + bv1, 0.f) * sc1 + sh1;
                }
                uint32_t hp, lp;
                split_pack2(t0, t1, hp, lp);
                int off = r * ASTRIDE + c * 2;
                *(uint32_t*)(smem + SM_A + off)         = hp;
                *(uint32_t*)(smem + SM_A + 17408 + off) = lp;
                split_pack2(t2, t3, hp, lp);
                off += 8 * ASTRIDE;
                *(uint32_t*)(smem + SM_A + off)         = hp;
                *(uint32_t*)(smem + SM_A + 17408 + off) = lp;
            }
        }
    }
    CP_WAIT0();
    __syncthreads();

#pragma unroll
    for (int a = 0; a < 2; a++)
#pragma unroll
        for (int b = 0; b < 4; b++)
#pragma unroll
            for (int c = 0; c < 4; c++) acc[a][b][c] = 0.f;

    gemm_core(sb + SM_A, sb + SM_W, mrow0, ncol0, lane, acc);
    __syncthreads();   // all warps done with smem reads; W/A regions reusable

    // ---- epilogue 2: h = relu(d + bb2); h1 store (conv1); stage h in smem --
    float* hbuf = (float*)(smem + SM_W);   // [64][HB_STRIDE]
    int* bids = rp;                        // reuse rowptr cache region
    {
        const int is64 = g_is64;
        if (tid < MROWS) {
            int grow = row0 + tid;
            bids[tid] = (grow < NN) ? load_index(batch, grow, is64) : -1;
        }
        const int rl = mrow0 + (lane >> 2);
        const int cl = (lane & 3) * 2;
#pragma unroll
        for (int mi = 0; mi < 2; mi++) {
            int ra = rl + mi * 16;      // local rows ra, ra+8
            int ga = row0 + ra;
            int gb = ga + 8;
#pragma unroll
            for (int ni = 0; ni < 4; ni++) {
                int c = ncol0 + ni * 8 + cl;
                float bv0 = g_bb2v[L][c], bv1 = g_bb2v[L][c + 1];
                float h0 = fmaxf(acc[mi][ni][0] + bv0, 0.f);
                float h1 = fmaxf(acc[mi][ni][1] + bv1, 0.f);
                float h2 = fmaxf(acc[mi][ni][2] + bv0, 0.f);
                float h3 = fmaxf(acc[mi][ni][3] + bv1, 0.f);
                *(float2*)(hbuf + ra * HB_STRIDE + c)       = make_float2(h0, h1);
                *(float2*)(hbuf + (ra + 8) * HB_STRIDE + c) = make_float2(h2, h3);
                if (CONV == 1) {
                    if (ga < NN)
                        *(float2*)(g_h1 + (size_t)ga * HH + c) = make_float2(h0, h1);
                    if (gb < NN)
                        *(float2*)(g_h1 + (size_t)gb * HH + c) = make_float2(h2, h3);
                }
            }
        }
    }
    __syncthreads();

    // ---- segmented pool reduction: one atomic per (graph-segment, column) --
    {
        const int col = tid & 127;
        const int r0 = (tid >> 7) * 32;
        float sum = 0.f;
        int cur = bids[r0];
#pragma unroll 4
        for (int r = r0; r < r0 + 32; r++) {
            int b = bids[r];
            if (b != cur) {
                if (cur >= 0) red_add_f32(pool + (size_t)cur * HH + col, sum);
                sum = 0.f;
                cur = b;
            }
            sum += hbuf[r * HB_STRIDE + col];
        }
        if (cur >= 0) red_add_f32(pool + (size_t)cur * HH + col, sum);
    }
}

// ---------------- head: relu([p1,p2]@Wl1 + bl1) @ Wl2 + bl2 ----------------
#define HZ_STRIDE 264
#define HEAD_SMEM ((256 * 64 + 4 * HZ_STRIDE + 64 * CC + 64 + 16) * 4)

__global__ void __launch_bounds__(128)
head_kernel(const float* __restrict__ Wl1, const float* __restrict__ bl1,
            const float* __restrict__ Wl2, const float* __restrict__ bl2,
            float* __restrict__ out) {
    extern __shared__ float smemf[];
    float* Wl1s = smemf;                        // [256][64]
    float* zs   = smemf + 256 * 64;             // [4][HZ_STRIDE]
    float* Wl2s = zs + 4 * HZ_STRIDE;           // [64][10]
    float* bl1s = Wl2s + 64 * CC;               // [64]
    float* bl2s = bl1s + 64;                    // [10]

    int tid = threadIdx.x;
    for (int i = tid; i < 4 * 256; i += 128) {
        int w = i >> 8, k = i & 255;
        int r = blockIdx.x * 4 + w;
        float v = 0.f;
        if (r < GG)
            v = (k < 128) ? g_p[(size_t)r * HH + k]
                          : g_p[GG * HH + (size_t)r * HH + (k - 128)];
        zs[w * HZ_STRIDE + k] = v;
    }
    for (int i = tid; i < 256 * 64 / 4; i += 128)
        ((float4*)Wl1s)[i] = ((const float4*)Wl1)[i];
    for (int i = tid; i < 64 * CC; i += 128) Wl2s[i] = Wl2[i];
    if (tid < 64) bl1s[tid] = bl1[tid];
    else if (tid < 64 + CC) bl2s[tid - 64] = bl2[tid - 64];
    __syncthreads();

    int lane = tid & 31;
    int warp = tid >> 5;
    int r = blockIdx.x * 4 + warp;
    if (r >= GG) return;

    float h0 = bl1s[2 * lane], h1v = bl1s[2 * lane + 1];
    const float* z = zs + warp * HZ_STRIDE;
#pragma unroll 8
    for (int k = 0; k < 256; ++k) {
        float v = z[k];
        float2 w = ((const float2*)Wl1s)[k * 32 + lane];
        h0 += v * w.x; h1v += v * w.y;
    }
    h0 = fmaxf(h0, 0.f); h1v = fmaxf(h1v, 0.f);

#pragma unroll
    for (int c = 0; c < CC; c++) {
        float part = h0 * Wl2s[(2 * lane) * CC + c] + h1v * Wl2s[(2 * lane + 1) * CC + c];
#pragma unroll
        for (int off = 16; off; off >>= 1)
            part += __shfl_xor_sync(0xffffffffu, part, off);
        if (lane == 0) out[r * CC + c] = part + bl2s[c];
    }
}

// ---------------- launch ----------------------------------------------------
extern "C" void kernel_launch(void* const* d_in, const int* in_sizes, int n_in,
                              void* d_out, int out_size) {
    const float* x    = (const float*)d_in[0];
    const void*  eidx = d_in[1];
    const void*  batch= d_in[2];
    const float* W1a  = (const float*)d_in[3];
    const float* b1a  = (const float*)d_in[4];
    const float* g1   = (const float*)d_in[5];
    const float* be1  = (const float*)d_in[6];
    const float* m1   = (const float*)d_in[7];
    const float* v1   = (const float*)d_in[8];
    const float* W1b  = (const float*)d_in[9];
    const float* b1b  = (const float*)d_in[10];
    const float* W2a  = (const float*)d_in[11];
    const float* b2a  = (const float*)d_in[12];
    const float* g2   = (const float*)d_in[13];
    const float* be2  = (const float*)d_in[14];
    const float* m2   = (const float*)d_in[15];
    const float* v2   = (const float*)d_in[16];
    const float* W2b  = (const float*)d_in[17];
    const float* b2b  = (const float*)d_in[18];
    const float* Wl1  = (const float*)d_in[19];
    const float* bl1  = (const float*)d_in[20];
    const float* Wl2  = (const float*)d_in[21];
    const float* bl2  = (const float*)d_in[22];
    float* out = (float*)d_out;

    cudaFuncSetAttribute(mlp_kernel<1>, cudaFuncAttributeMaxDynamicSharedMemorySize, MLP_SMEM);
    cudaFuncSetAttribute(mlp_kernel<2>, cudaFuncAttributeMaxDynamicSharedMemorySize, MLP_SMEM);
    cudaFuncSetAttribute(head_kernel,   cudaFuncAttributeMaxDynamicSharedMemorySize, HEAD_SMEM);

    zero_kernel<<<256, 256>>>(
        (const int*)eidx, W1a, W1b, W2a, W2b,
        b1a, b1b, g1, be1, m1, v1, b2a, b2b, g2, be2, m2, v2);

    int egrid = (EE + 256 * EB - 1) / (256 * EB);
    deg_kernel<<<egrid, 256>>>(eidx);
    sums_kernel<<<NCHUNK, 1024>>>();
    apply_kernel<<<NCHUNK, 1024>>>();
    fill_kernel<<<egrid, 256>>>(eidx);

    mlp_kernel<1><<<(NN + MROWS - 1) / MROWS, 256, MLP_SMEM>>>(x, batch);
    mlp_kernel<2><<<(NN + MROWS - 1) / MROWS, 256, MLP_SMEM>>>(x /*unused*/, batch);

    head_kernel<<<125, 128, HEAD_SMEM>>>(Wl1, bl1, Wl2, bl2, out);
}